// round 1
// baseline (speedup 1.0000x reference)
#include <cuda_runtime.h>
#include <cub/cub.cuh>

// Problem constants (fixed by setup_inputs)
#define BB 4
#define NN 131072
#define BN (BB * NN)          // 524288
// components per point: means 3 + cov 9 + harm 75 + opac 1 = 88

// -------- device scratch (static: no allocations allowed) --------
__device__ unsigned g_min_u, g_max_u;
__device__ unsigned g_keys_in[BN];
__device__ unsigned g_keys_out[BN];
__device__ unsigned g_vals_in[BN];
__device__ unsigned g_vals_out[BN];
__device__ int      g_scan[BN];
__device__ float    g_w[BN];         // softmax weight per SORTED slot
__device__ int      g_segstart[BN];  // sorted index of head of segment m (per batch)
__device__ int      g_uniq[BB];
__device__ unsigned char g_temp[32u * 1024u * 1024u]; // cub temp storage

// -------- float <-> order-preserving unsigned --------
__device__ __forceinline__ unsigned f2ord(float f) {
    unsigned u = __float_as_uint(f);
    return (u & 0x80000000u) ? ~u : (u | 0x80000000u);
}
__device__ __forceinline__ float ord2f(unsigned u) {
    return __uint_as_float((u & 0x80000000u) ? (u & 0x7fffffffu) : ~u);
}

__global__ void k_init() {
    g_min_u = 0xFFFFFFFFu;
    g_max_u = 0u;
}

__global__ void k_minmax(const float* __restrict__ means) {
    unsigned lo = 0xFFFFFFFFu, hi = 0u;
    for (int i = blockIdx.x * blockDim.x + threadIdx.x; i < BN * 3;
         i += gridDim.x * blockDim.x) {
        unsigned o = f2ord(__ldg(&means[i]));
        lo = min(lo, o);
        hi = max(hi, o);
    }
#pragma unroll
    for (int s = 16; s; s >>= 1) {
        lo = min(lo, __shfl_xor_sync(0xFFFFFFFFu, lo, s));
        hi = max(hi, __shfl_xor_sync(0xFFFFFFFFu, hi, s));
    }
    if ((threadIdx.x & 31) == 0) {
        atomicMin(&g_min_u, lo);
        atomicMax(&g_max_u, hi);
    }
}

// Build 32-bit sort keys: (batch<<30) | linear voxel id  (lin < 1e9 < 2^30).
// Float math forced to IEEE RN so fast-math flags cannot flip floor() results.
__global__ void k_keys(const float* __restrict__ means) {
    int p = blockIdx.x * blockDim.x + threadIdx.x;
    if (p >= BN) return;
    float mmin = ord2f(g_min_u);
    float mmax = ord2f(g_max_u);
    float rng = __fsub_rn(mmax, mmin);
    long long vn = (long long)floorf(__fdiv_rn(rng, 0.001f)) + 1;
    if (vn > 1000) vn = 1000;
    if (vn < 1) vn = 1;
    float vnf = (float)vn;
    float den = __fadd_rn(rng, 1e-6f);
    unsigned lin = 0;
#pragma unroll
    for (int d = 0; d < 3; ++d) {
        float m = __ldg(&means[p * 3 + d]);
        float nrm = __fdiv_rn(__fsub_rn(m, mmin), den);
        long long v = (long long)floorf(__fmul_rn(nrm, vnf));
        if (v < 0) v = 0;
        if (v > vn - 1) v = vn - 1;
        lin = lin * (unsigned)vn + (unsigned)v;
    }
    unsigned b = (unsigned)(p / NN);
    g_keys_in[p] = (b << 30) | lin;
    g_vals_in[p] = (unsigned)p;
}

__global__ void k_flags() {
    int i = blockIdx.x * blockDim.x + threadIdx.x;
    if (i >= BN) return;
    int f = 0;
    if (i % NN != 0) f = (g_keys_out[i] != g_keys_out[i - 1]) ? 1 : 0;
    g_scan[i] = f;
}

// Phase A: per sorted slot compute softmax weight; segment heads record their
// sorted start index at g_segstart[b*N + rank]. Last slot per batch records uniq.
__global__ void k_phaseA(const float* __restrict__ scores) {
    int i = blockIdx.x * blockDim.x + threadIdx.x;
    if (i >= BN) return;
    int b = i / NN;
    if ((i + 1) % NN == 0) g_uniq[b] = g_scan[i] - g_scan[b * NN] + 1;

    unsigned k = g_keys_out[i];
    bool head = (i % NN == 0) || (g_keys_out[i - 1] != k);
    if (!head) return;

    int bend = (b + 1) * NN;
    int e = i + 1;
    while (e < bend && g_keys_out[e] == k) ++e;

    int m = g_scan[i] - g_scan[b * NN];  // dense rank within batch
    g_segstart[b * NN + m] = i;

    if (e == i + 1) {
        g_w[i] = 1.0f;  // singleton: exp(0)/exp(0)
    } else {
        float mx = __int_as_float(0xff800000);  // -inf
        for (int j = i; j < e; ++j)
            mx = fmaxf(mx, __ldg(&scores[g_vals_out[j]]));
        float den = 0.0f;
        for (int j = i; j < e; ++j)
            den += expf(__ldg(&scores[g_vals_out[j]]) - mx);
        for (int j = i; j < e; ++j)
            g_w[j] = expf(__ldg(&scores[g_vals_out[j]]) - mx) / den;
    }
}

// Phase B: each block produces 32 consecutive output rows of one batch.
// Gather member points into shared (weighted), then coalesced contiguous writes.
// Rows >= uniq stay zero (acc initialized to 0) -> tail handled for free.
__global__ __launch_bounds__(256) void k_phaseB(
    const float* __restrict__ means, const float* __restrict__ cov,
    const float* __restrict__ harm, const float* __restrict__ opac,
    float* __restrict__ out) {
    __shared__ float acc[32][89];  // 88 comps + pad

    int r0 = blockIdx.x * 32;  // global row base; N % 32 == 0 -> one batch per block
    int b = r0 / NN;
    int uniq = g_uniq[b];
    int t = threadIdx.x;

    for (int idx = t; idx < 32 * 89; idx += 256) (&acc[0][0])[idx] = 0.0f;
    __syncthreads();

    int row = t >> 3;   // 0..31
    int tx = t & 7;     // 8 threads per row
    int m = (r0 - b * NN) + row;
    if (m < uniq) {
        int start = g_segstart[b * NN + m];
        int end = (m + 1 < uniq) ? g_segstart[b * NN + m + 1] : (b + 1) * NN;
        for (int j = start; j < end; ++j) {
            int p = (int)g_vals_out[j];
            float w = g_w[j];
            if (tx < 3) acc[row][tx] += w * __ldg(&means[p * 3 + tx]);
            for (int cc = tx; cc < 9; cc += 8)
                acc[row][3 + cc] += w * __ldg(&cov[p * 9 + cc]);
#pragma unroll
            for (int cc = tx; cc < 75; cc += 8)
                acc[row][12 + cc] += w * __ldg(&harm[p * 75 + cc]);
            if (tx == 0) acc[row][87] += w * __ldg(&opac[p]);
        }
    }
    __syncthreads();

    float* out_means = out;
    float* out_cov = out + (size_t)3 * BN;
    float* out_harm = out + (size_t)12 * BN;
    float* out_opac = out + (size_t)87 * BN;

    if (t < 96) out_means[(size_t)r0 * 3 + t] = acc[t / 3][t % 3];
    for (int idx = t; idx < 288; idx += 256)
        out_cov[(size_t)r0 * 9 + idx] = acc[idx / 9][3 + idx % 9];
    for (int idx = t; idx < 2400; idx += 256)
        out_harm[(size_t)r0 * 75 + idx] = acc[idx / 75][12 + idx % 75];
    if (t < 32) out_opac[r0 + t] = acc[t][87];
}

extern "C" void kernel_launch(void* const* d_in, const int* in_sizes, int n_in,
                              void* d_out, int out_size) {
    const float* scores = (const float*)d_in[0];  // [B,N,1]
    const float* means  = (const float*)d_in[1];  // [B,N,3]
    const float* cov    = (const float*)d_in[2];  // [B,N,3,3]
    const float* harm   = (const float*)d_in[3];  // [B,N,3,25]
    const float* opac   = (const float*)d_in[4];  // [B,N]
    float* out = (float*)d_out;

    void *pki, *pko, *pvi, *pvo, *pscan, *ptemp;
    cudaGetSymbolAddress(&pki, g_keys_in);
    cudaGetSymbolAddress(&pko, g_keys_out);
    cudaGetSymbolAddress(&pvi, g_vals_in);
    cudaGetSymbolAddress(&pvo, g_vals_out);
    cudaGetSymbolAddress(&pscan, g_scan);
    cudaGetSymbolAddress(&ptemp, g_temp);

    k_init<<<1, 32>>>();
    k_minmax<<<512, 256>>>(means);
    k_keys<<<BN / 256, 256>>>(means);

    size_t tmp_bytes = 0;
    cub::DeviceRadixSort::SortPairs(nullptr, tmp_bytes,
                                    (const unsigned*)pki, (unsigned*)pko,
                                    (const unsigned*)pvi, (unsigned*)pvo,
                                    BN, 0, 32);
    if (tmp_bytes > sizeof(g_temp)) tmp_bytes = sizeof(g_temp);  // (fits in practice)
    cub::DeviceRadixSort::SortPairs(ptemp, tmp_bytes,
                                    (const unsigned*)pki, (unsigned*)pko,
                                    (const unsigned*)pvi, (unsigned*)pvo,
                                    BN, 0, 32);

    k_flags<<<BN / 256, 256>>>();

    size_t tmp2 = 0;
    cub::DeviceScan::InclusiveSum(nullptr, tmp2, (int*)pscan, (int*)pscan, BN);
    if (tmp2 > sizeof(g_temp)) tmp2 = sizeof(g_temp);
    cub::DeviceScan::InclusiveSum(ptemp, tmp2, (int*)pscan, (int*)pscan, BN);

    k_phaseA<<<BN / 256, 256>>>(scores);
    k_phaseB<<<BN / 32, 256>>>(means, cov, harm, opac, out);
}